// round 13
// baseline (speedup 1.0000x reference)
#include <cuda_runtime.h>

// PolyphaseDiff: resample_poly(x, up=3, down=2), 129-tap FIR.
// out[j] = sum_c a_pf[c] * x[i0-42+c], t=64+2j, pf=t%3, i0=t/3, a_pf[c]=3h[pf+126-3c].
//
// Compute core (validated R5-R12): one f32x2 loop for all 3 output classes,
//   acc[r] += T[p][k] * tq[8u + r + k], k=0..21,
// tile as u64 pairs in padded smem (9u + immediate addressing, LDS.64
// conflict-free), taps phase-folded per class, cp.async double-buffered tiles.
//
// R13: fix the REAL staging conflict. sh_out[24u+3r+p] has lane stride 24
// words -> banks {0,24,16,8} -> 8-way conflict -> 64 wavefronts/warp-tile,
// the largest L1tex consumer. New layout sh_out[25u + 3r + p]: odd stride 25,
// gcd(25,32)=1 -> conflict-free STS (8 wf). Reader skips the 1-in-25 pad word
// (scalar epilogue, div-by-25) - spends idle ALU to buy back L1tex wavefronts.

#define RR 8                 // outputs per thread
#define NP 22                // tap pairs per class
#define LOOKAHEAD 8          // window pairs preloaded (1-step stagger)
#define THREADS 192          // 6 warps: warp w -> class w%3
#define NOUT_BLK 1536        // outputs per tile = 3 * 64 * RR
#define TPB 2                // tiles per block
#define TQ 536               // u64 pairs per tile
#define TQ_ALLOC (TQ + TQ / 8 + 2)
#define TILE_F (TQ * 2)      // 1072 floats per tile
#define SOUT 1600            // 64 rows * 25 (24 data + 1 pad)

typedef unsigned long long u64;

#define FMA_X2(d, a, b, c) \
    asm("fma.rn.f32x2 %0, %1, %2, %3;" : "=l"(d) : "l"(a), "l"(b), "l"(c))
#define PACK_X2(d, lo, hi) \
    asm("mov.b64 %0, {%1, %2};" : "=l"(d) : "f"(lo), "f"(hi))
#define UNPACK_X2(lo, hi, s) \
    asm("mov.b64 {%0, %1}, %2;" : "=f"(lo), "=f"(hi) : "l"(s))

#define CP_ASYNC4(dst_u32, src_ptr) \
    asm volatile("cp.async.ca.shared.global [%0], [%1], 4;" \
                 :: "r"(dst_u32), "l"(src_ptr))
#define CP_COMMIT() asm volatile("cp.async.commit_group;" ::: "memory")
#define CP_WAIT0()  asm volatile("cp.async.wait_group 0;" ::: "memory")
#define BAR_HALF(id) \
    asm volatile("bar.sync %0, 96;" :: "r"(id) : "memory")

__device__ __forceinline__ int SP(int i) { return i + (i >> 3); }

// Load tile tt into buf. Interior tiles: 4B cp.async into the padded pair
// layout (dst float offset f + 2*(f>>4) == pair layout since (2i+b)>>4 == i>>3).
// Edge tiles: guarded scalar fallback.
__device__ __forceinline__ void load_tile(u64* buf, const float* __restrict__ x,
                                          int tt, int tid, int N)
{
    const int IB = 1024 * tt - 21;
    if (IB >= 0 && IB + TILE_F <= N) {
        unsigned base = (unsigned)__cvta_generic_to_shared(buf);
        #pragma unroll
        for (int q = 0; q < 6; ++q) {
            int f = tid + q * THREADS;
            if (f < TILE_F) {
                unsigned dst = base + 4u * (unsigned)(f + 2 * (f >> 4));
                CP_ASYNC4(dst, x + IB + f);
            }
        }
    } else {
        for (int i = tid; i < TQ; i += THREADS) {
            int g0 = IB + 2 * i, g1 = g0 + 1;
            float lo = (g0 >= 0 && g0 < N) ? x[g0] : 0.0f;
            float hi = (g1 >= 0 && g1 < N) ? x[g1] : 0.0f;
            u64 d; PACK_X2(d, lo, hi);
            buf[SP(i)] = d;
        }
    }
}

__global__ __launch_bounds__(THREADS, 7)
void poly_resample_kernel(const float* __restrict__ x,
                          const float* __restrict__ h,
                          float* __restrict__ out,
                          int N, int n_out, int n_tiles)
{
    __shared__ __align__(16) u64   sh2[2][TQ_ALLOC];   // double-buffered tile
    __shared__ __align__(16) u64   sh_t[3 * NP];       // tap pairs per class
    __shared__ __align__(16) float sh_out[SOUT];       // padded-row staging

    const int tid = threadIdx.x;

    // ---- pack taps: class p uses filter phase pf = (1+2p)%3 ----
    if (tid < 3 * NP) {
        int p = tid / NP, k = tid % NP;
        int pf = (1 + 2 * p) % 3;             // {1,0,2}
        float lo, hi;
        if (p == 0) {                         // (a[2k], a[2k+1]), zero tail
            lo = 3.0f * h[127 - 6 * k];
            hi = (k < 21) ? 3.0f * h[124 - 6 * k] : 0.0f;
        } else if (k == 0) {                  // head pair (0, a[0])
            lo = 0.0f;
            hi = 3.0f * h[pf + 126];
        } else {                              // (a[2k-1], a[2k])
            lo = 3.0f * h[pf + 129 - 6 * k];
            hi = 3.0f * h[pf + 126 - 6 * k];
        }
        u64 d; PACK_X2(d, lo, hi);
        sh_t[tid] = d;
    }

    const int t0 = blockIdx.x * TPB;
    const int ntloc = min(TPB, n_tiles - t0);

    // ---- prologue: tile t0 into buffer 0 ----
    load_tile(sh2[0], x, t0, tid, N);
    CP_COMMIT(); CP_WAIT0();
    __syncthreads();

    const int wid  = tid >> 5;
    const int lane = tid & 31;
    const int p    = wid % 3;                 // class = j mod 3 (uniform/warp)
    const int u    = (wid / 3) * 32 + lane;   // 0..63 within class
    const int half = (tid < 96) ? 0 : 1;      // warp triple; u<32 <-> half 0
    const int th   = tid - half * 96;
    const u64* __restrict__ T = sh_t + p * NP;

    int cur = 0;
    for (int t = 0; t < ntloc; ++t) {
        const int tt = t0 + t;
        const bool hasnext = (t + 1 < ntloc);

        // async-fill next buffer while this tile computes
        if (hasnext)
            load_tile(sh2[cur ^ 1], x, tt + 1, tid, N);
        CP_COMMIT();

        // ---- compute tile tt from sh2[cur] ----
        const u64* __restrict__ wb = &sh2[cur][0] + 9 * u;

        u64 wp[29];
        #pragma unroll
        for (int m = 0; m < LOOKAHEAD; ++m)
            wp[m] = wb[m + (m >> 3)];

        u64 acc[RR];
        #pragma unroll
        for (int r = 0; r < RR; ++r) acc[r] = 0ull;

        #pragma unroll
        for (int k = 0; k < NP; ++k) {
            if (k + LOOKAHEAD < 29) {
                const int m = k + LOOKAHEAD;
                wp[m] = wb[m + (m >> 3)];
            }
            const u64 tp = T[k];               // uniform -> LDS.64 broadcast
            #pragma unroll
            for (int r = 0; r < RR; ++r)
                FMA_X2(acc[r], tp, wp[k + r], acc[r]);
        }

        // stage outputs: row stride 25 (odd) -> lane stride 25, conflict-free
        const int row = 25 * u + p;
        #pragma unroll
        for (int r = 0; r < RR; ++r) {
            float e, o; UNPACK_X2(e, o, acc[r]);
            sh_out[row + 3 * r] = e + o;
        }
        if (half == 0) BAR_HALF(1); else BAR_HALF(2);

        // epilogue: each half drains its own 800 words (u<32 <-> words<800),
        // skipping the 1-in-25 pad word; global stores stay near-coalesced.
        const int Jb = tt * NOUT_BLK;
        const int m0 = half * 800;
        #pragma unroll
        for (int i = 0; i < 9; ++i) {
            int mm = th + i * 96;
            if (mm < 800) {
                int m  = m0 + mm;
                int uu = m / 25;
                int rem = m - 25 * uu;
                if (rem < 24) {
                    int j = Jb + 24 * uu + rem;
                    if (j < n_out) out[j] = sh_out[m];
                }
            }
        }

        // drain async fill, publish next buffer (also protects sh_out reuse)
        if (hasnext) {
            CP_WAIT0();
            __syncthreads();
        }
        cur ^= 1;
    }
}

extern "C" void kernel_launch(void* const* d_in, const int* in_sizes, int n_in,
                              void* d_out, int out_size)
{
    const float* x = (const float*)d_in[0];
    const float* h = (const float*)d_in[1];
    float* out = (float*)d_out;

    const int N = in_sizes[0];
    const int n_out = out_size;
    const int n_tiles = (n_out + NOUT_BLK - 1) / NOUT_BLK;       // 2048
    const int grid = (n_tiles + TPB - 1) / TPB;                  // 1024

    poly_resample_kernel<<<grid, THREADS>>>(x, h, out, N, n_out, n_tiles);
}

// round 14
// speedup vs baseline: 1.3233x; 1.3233x over previous
#include <cuda_runtime.h>

// PolyphaseDiff: resample_poly(x, up=3, down=2), 129-tap FIR.
// out[j] = sum_c a_pf[c] * x[i0-42+c], t=64+2j, pf=t%3, i0=t/3, a_pf[c]=3h[pf+126-3c].
//
// Core (R5-R12): one f32x2 loop for all 3 classes: acc[r] += T[p][k]*tq[8u+r+k],
// k=0..21; cp.async double-buffered tiles (TPB=2); taps phase-folded per class.
//
// R14:
//  - tile pad 2-pairs-per-8 (i + 2*(i>>3)): lane base 80B -> 16B aligned,
//    window loads become 15 conflict-free LDS.128 (was 29 LDS.64).
//  - staging rows stride 25 (odd -> conflict-free STS, from R13) + structured
//    reader: thread v owns row v/3, words 25*(v/3)+8*(v%3)+i -> no pads hit,
//    no div, 8 LDS.32 + 2 aligned STG.128 (fully coalesced).

#define RR 8
#define NP 22
#define THREADS 192          // 6 warps: warp w -> class w%3
#define NOUT_BLK 1536
#define TPB 2
#define TQ 536               // u64 pairs per tile
#define TQ_ALLOC (TQ + 2 * (TQ / 8) + 4)     // pad 2 per 8
#define TILE_F (TQ * 2)
#define SOUT 1600            // 64 rows * 25

typedef unsigned long long u64;

#define FMA_X2(d, a, b, c) \
    asm("fma.rn.f32x2 %0, %1, %2, %3;" : "=l"(d) : "l"(a), "l"(b), "l"(c))
#define PACK_X2(d, lo, hi) \
    asm("mov.b64 %0, {%1, %2};" : "=l"(d) : "f"(lo), "f"(hi))
#define UNPACK_X2(lo, hi, s) \
    asm("mov.b64 {%0, %1}, %2;" : "=f"(lo), "=f"(hi) : "l"(s))
#define LDS_V2U64(a, b, addr32) \
    asm volatile("ld.shared.v2.b64 {%0, %1}, [%2];" : "=l"(a), "=l"(b) : "r"(addr32))
#define CP_ASYNC4(dst_u32, src_ptr) \
    asm volatile("cp.async.ca.shared.global [%0], [%1], 4;" :: "r"(dst_u32), "l"(src_ptr))
#define CP_COMMIT() asm volatile("cp.async.commit_group;" ::: "memory")
#define CP_WAIT0()  asm volatile("cp.async.wait_group 0;" ::: "memory")
#define BAR_HALF(id) asm volatile("bar.sync %0, 96;" :: "r"(id) : "memory")

__device__ __forceinline__ int SPp(int i) { return i + 2 * (i >> 3); }

__global__ __launch_bounds__(THREADS, 6)
void poly_resample_kernel(const float* __restrict__ x,
                          const float* __restrict__ h,
                          float* __restrict__ out,
                          int N, int n_out, int n_tiles)
{
    __shared__ __align__(16) u64   sh2[2][TQ_ALLOC];
    __shared__ __align__(16) u64   sh_t[3 * NP];
    __shared__ __align__(16) float sh_out[SOUT];

    const int tid = threadIdx.x;

    // ---- pack taps: class p uses filter phase pf = (1+2p)%3 ----
    if (tid < 3 * NP) {
        int p = tid / NP, k = tid % NP;
        int pf = (1 + 2 * p) % 3;             // {1,0,2}
        float lo, hi;
        if (p == 0) {
            lo = 3.0f * h[127 - 6 * k];
            hi = (k < 21) ? 3.0f * h[124 - 6 * k] : 0.0f;
        } else if (k == 0) {
            lo = 0.0f;
            hi = 3.0f * h[pf + 126];
        } else {
            lo = 3.0f * h[pf + 129 - 6 * k];
            hi = 3.0f * h[pf + 126 - 6 * k];
        }
        u64 d; PACK_X2(d, lo, hi);
        sh_t[tid] = d;
    }

    const int t0 = blockIdx.x * TPB;
    const int ntloc = min(TPB, n_tiles - t0);

    // hoisted cp.async addressing: 6 dst offsets (padded layout), 6 src offsets
    const unsigned sh2b = (unsigned)__cvta_generic_to_shared(&sh2[0][0]);
    unsigned dstoff[6];
    #pragma unroll
    for (int q = 0; q < 6; ++q) {
        int f = tid + q * THREADS;
        dstoff[q] = (f < TILE_F) ? 4u * (unsigned)(f + 4 * (f >> 4)) : 0xFFFFFFFFu;
    }

    // ---- tile loader ----
    auto load_tile = [&](int buf, int tt) {
        const int IB = 1024 * tt - 21;
        unsigned base = sh2b + (unsigned)(buf * (TQ_ALLOC * 8));
        if (IB >= 0 && IB + TILE_F <= N) {
            const float* src = x + IB + tid;
            #pragma unroll
            for (int q = 0; q < 6; ++q)
                if (dstoff[q] != 0xFFFFFFFFu)
                    CP_ASYNC4(base + dstoff[q], src + q * THREADS);
        } else {
            u64* b = sh2[buf];
            for (int i = tid; i < TQ; i += THREADS) {
                int g0 = IB + 2 * i, g1 = g0 + 1;
                float lo = (g0 >= 0 && g0 < N) ? x[g0] : 0.0f;
                float hi = (g1 >= 0 && g1 < N) ? x[g1] : 0.0f;
                u64 d; PACK_X2(d, lo, hi);
                b[SPp(i)] = d;
            }
        }
    };

    load_tile(0, t0);
    CP_COMMIT(); CP_WAIT0();
    __syncthreads();

    const int wid  = tid >> 5;
    const int lane = tid & 31;
    const int p    = wid % 3;                 // class (uniform per warp)
    const int u    = (wid / 3) * 32 + lane;   // 0..63
    const int half = (tid < 96) ? 0 : 1;      // u<32 <-> half 0
    const int th   = tid - half * 96;
    const u64* __restrict__ T = sh_t + p * NP;

    // epilogue reader constants: thread owns row tid/3, 8 words
    const int r_uu  = tid / 3;
    const int r_sub = tid - 3 * r_uu;
    const int r_row = 25 * r_uu + 8 * r_sub;  // smem word base (never a pad)
    const int r_j   = 24 * r_uu + 8 * r_sub;  // global offset base

    int cur = 0;
    for (int t = 0; t < ntloc; ++t) {
        const int tt = t0 + t;
        const bool hasnext = (t + 1 < ntloc);

        if (hasnext) load_tile(cur ^ 1, tt + 1);
        CP_COMMIT();

        // ---- compute tile tt: window via LDS.128, base pair 10u (80B) ----
        const unsigned wb32 = sh2b + (unsigned)(cur * (TQ_ALLOC * 8)) + 80u * (unsigned)u;

        u64 wp[30];
        #pragma unroll
        for (int m = 0; m < 10; m += 2)       // preload wp[0..9]
            LDS_V2U64(wp[m], wp[m + 1], wb32 + 8u * (unsigned)(m + 2 * (m >> 3)));

        u64 acc[RR];
        #pragma unroll
        for (int r = 0; r < RR; ++r) acc[r] = 0ull;

        #pragma unroll
        for (int k = 0; k < NP; ++k) {
            if ((k & 1) == 0 && k <= 18) {    // fetch pairs (k+10, k+11)
                const int m = k + 10;
                LDS_V2U64(wp[m], wp[m + 1], wb32 + 8u * (unsigned)(m + 2 * (m >> 3)));
            }
            const u64 tp = T[k];              // uniform -> LDS.64 broadcast
            #pragma unroll
            for (int r = 0; r < RR; ++r)
                FMA_X2(acc[r], tp, wp[k + r], acc[r]);
        }

        // stage: row stride 25 (odd) -> conflict-free STS
        const int row = 25 * u + p;
        #pragma unroll
        for (int r = 0; r < RR; ++r) {
            float e, o; UNPACK_X2(e, o, acc[r]);
            sh_out[row + 3 * r] = e + o;
        }
        if (half == 0) BAR_HALF(1); else BAR_HALF(2);

        // structured reader: 8 scalar LDS (no pads) + 2 aligned STG.128
        const int Jb = tt * NOUT_BLK;
        {
            float v[8];
            #pragma unroll
            for (int i = 0; i < 8; ++i)
                v[i] = sh_out[r_row + i];
            if (Jb + NOUT_BLK <= n_out) {
                float4* o4 = (float4*)(out + Jb + r_j);
                o4[0] = make_float4(v[0], v[1], v[2], v[3]);
                o4[1] = make_float4(v[4], v[5], v[6], v[7]);
            } else {
                #pragma unroll
                for (int i = 0; i < 8; ++i) {
                    int j = Jb + r_j + i;
                    if (j < n_out) out[j] = v[i];
                }
            }
        }

        if (hasnext) {
            CP_WAIT0();
            __syncthreads();
        }
        cur ^= 1;
    }
}

extern "C" void kernel_launch(void* const* d_in, const int* in_sizes, int n_in,
                              void* d_out, int out_size)
{
    const float* x = (const float*)d_in[0];
    const float* h = (const float*)d_in[1];
    float* out = (float*)d_out;

    const int N = in_sizes[0];
    const int n_out = out_size;
    const int n_tiles = (n_out + NOUT_BLK - 1) / NOUT_BLK;       // 2048
    const int grid = (n_tiles + TPB - 1) / TPB;                  // 1024

    poly_resample_kernel<<<grid, THREADS>>>(x, h, out, N, n_out, n_tiles);
}